// round 2
// baseline (speedup 1.0000x reference)
#include <cuda_runtime.h>
#include <math.h>

#define NTOT 2010
#define QD 8
#define LTW 10
#define DIN 80
#define NH 2000
#define MI 256
#define DO 16
#define NCHUNK 30
#define CHUNK 67
#define JITTERF 1.0e-4f

// ---------------- device scratch (static, no allocation) ----------------
__device__ float g_P[NH*DIN], g_R[NH*DIN], g_U[NH*DIN], g_W[NH*DIN];
__device__ float g_a1[NH], g_lc1[NH], g_h[NH];
__device__ float g_F[NH*MI];
__device__ float g_psi1T[MI*NH];
__device__ float g_Kuu[MI*MI];
__device__ float g_LT[MI*MI];
__device__ float g_pd[MI*MI];
__device__ float g_part[NCHUNK*MI*MI];
__device__ float g_psi2[MI*MI];
__device__ float g_A[MI*NH];
__device__ float g_tmp[MI*MI];
__device__ float g_tmpT[MI*MI];
__device__ float g_AAT[MI*MI];
__device__ float g_Bm[MI*MI];
__device__ float g_LBT[MI*MI];
__device__ float g_AY[MI*DO];
__device__ float g_cmat[MI*DO];

__constant__ int c_ta[10] = {0,0,0,0,1,1,1,2,2,3};
__constant__ int c_tb[10] = {0,1,2,3,1,2,3,2,3,3};

// ---------------- per-n preprocessing (hankel + per-row stats) ----------------
__global__ void k_prep(const float* __restrict__ Xm, const float* __restrict__ Xv,
                       const float* __restrict__ ls) {
    int n = blockIdx.x, t = threadIdx.x;
    float4 v = make_float4(0.f, 0.f, 0.f, 0.f);
    if (t < DIN) {
        int l = t / QD, q = t - l * QD;
        float xm = Xm[(1 + n + l) * QD + q];
        float xv = Xv[(1 + n + l) * QD + q];
        float lsv = ls[t];
        float ls2 = lsv * lsv;
        float d1 = xv + ls2, d2 = 2.f * xv + ls2;
        float id1 = 1.f / d1, id2 = 1.f / d2;
        g_P[n*DIN + t] = xm * id1;
        g_R[n*DIN + t] = id1;
        g_U[n*DIN + t] = xm * id2;
        g_W[n*DIN + t] = id2;
        v.x = xm * xm * id1;
        v.y = log1pf(xv / ls2);
        v.z = xm * xm * id2;
        v.w = log1pf(2.f * xv / ls2);
    }
    __shared__ float4 sr[128];
    sr[t] = v;
    __syncthreads();
    for (int s = 64; s > 0; s >>= 1) {
        if (t < s) {
            float4 a = sr[t], b = sr[t + s];
            a.x += b.x; a.y += b.y; a.z += b.z; a.w += b.w;
            sr[t] = a;
        }
        __syncthreads();
    }
    if (t == 0) {
        float4 r = sr[0];
        g_a1[n]  = r.x;
        g_lc1[n] = -0.5f * r.y;
        g_h[n]   = -0.5f * r.w - r.z;   // logc2 - c2
    }
}

// ---------------- Kuu + kv^2*distfac ----------------
__global__ void k_kuu(const float* __restrict__ Z, const float* __restrict__ ls,
                      const float* __restrict__ kvp) {
    __shared__ float sZa[16][DIN+1], sZb[16][DIN+1], sil[DIN];
    int a0 = blockIdx.y * 16, b0 = blockIdx.x * 16;
    int tx = threadIdx.x, ty = threadIdx.y, tid = ty * 16 + tx;
    for (int i = tid; i < 16 * DIN; i += 256) {
        int r = i / DIN, q = i - r * DIN;
        sZa[r][q] = Z[(a0 + r) * DIN + q];
        sZb[r][q] = Z[(b0 + r) * DIN + q];
    }
    if (tid < DIN) { float L = ls[tid]; sil[tid] = 1.f / (L * L); }
    __syncthreads();
    float d2 = 0.f;
    #pragma unroll 16
    for (int q = 0; q < DIN; q++) {
        float d = sZa[ty][q] - sZb[tx][q];
        d2 = fmaf(d * d, sil[q], d2);
    }
    float kv = *kvp;
    int a = a0 + ty, b = b0 + tx;
    g_Kuu[a*MI + b] = kv * __expf(-0.5f * d2) + ((a == b) ? JITTERF : 0.f);
    g_pd[a*MI + b]  = kv * kv * __expf(-0.25f * d2);
}

// ---------------- psi1^T and F = exp(0.5h + t) ----------------
__global__ void k_psi1F(const float* __restrict__ Z, const float* __restrict__ kvp) {
    __shared__ float sZ[16][DIN+1], sZq[16][DIN+1];
    __shared__ float sP[16][DIN+1], sR[16][DIN+1], sU[16][DIN+1], sW[16][DIN+1];
    int m0 = blockIdx.x * 16, n0 = blockIdx.y * 16;
    int tx = threadIdx.x, ty = threadIdx.y, tid = ty * 16 + tx;
    for (int i = tid; i < 16 * DIN; i += 256) {
        int r = i / DIN, q = i - r * DIN;
        float z = Z[(m0 + r) * DIN + q];
        sZ[r][q] = z; sZq[r][q] = z * z;
        int ni = (n0 + r) * DIN + q;
        sP[r][q] = g_P[ni]; sR[r][q] = g_R[ni];
        sU[r][q] = g_U[ni]; sW[r][q] = g_W[ni];
    }
    __syncthreads();
    float pz = 0.f, rz = 0.f, uz = 0.f, wz = 0.f;
    #pragma unroll 8
    for (int q = 0; q < DIN; q++) {
        float z = sZ[tx][q], zq = sZq[tx][q];
        pz = fmaf(sP[ty][q], z,  pz);
        rz = fmaf(sR[ty][q], zq, rz);
        uz = fmaf(sU[ty][q], z,  uz);
        wz = fmaf(sW[ty][q], zq, wz);
    }
    int n = n0 + ty, m = m0 + tx;
    float kv = *kvp;
    g_psi1T[m*NH + n] = kv * __expf(fmaf(-0.5f, g_a1[n] - 2.f * pz + rz, g_lc1[n]));
    g_F[n*MI + m]     = __expf(0.5f * g_h[n] + uz - 0.25f * wz);
}

// ---------------- big psi2 kernel: sum_n F_a F_b exp(-0.5 * W-weighted <Za,Zb>) -----
__global__ void __launch_bounds__(256) k_psi2(const float* __restrict__ Z) {
    __shared__ __align__(16) float sZa[DIN][64];
    __shared__ __align__(16) float sZb[DIN][64];
    __shared__ float sW[DIN], sFa[64], sFb[64];
    int tp = blockIdx.x, ch = blockIdx.y;
    int a0 = c_ta[tp] * 64, b0 = c_tb[tp] * 64;
    int tid = threadIdx.x;
    for (int i = tid; i < 64 * DIN; i += 256) {
        int r = i & 63, q = i >> 6;
        sZa[q][r] = Z[(a0 + r) * DIN + q];
        sZb[q][r] = Z[(b0 + r) * DIN + q];
    }
    int tx = tid & 15, ty = tid >> 4;
    float acc[4][4] = {};
    int n0 = ch * CHUNK;
    int n1 = n0 + CHUNK; if (n1 > NH) n1 = NH;
    for (int n = n0; n < n1; n++) {
        __syncthreads();
        if (tid < DIN)                      sW[tid]        = g_W[n*DIN + tid];
        else if (tid >= 128 && tid < 192)   sFa[tid - 128] = g_F[n*MI + a0 + (tid - 128)];
        else if (tid >= 192)                sFb[tid - 192] = g_F[n*MI + b0 + (tid - 192)];
        __syncthreads();
        float C[4][4] = {};
        #pragma unroll 10
        for (int q = 0; q < DIN; q++) {
            float w = sW[q];
            float4 za = *(const float4*)(&sZa[q][tx * 4]);
            float4 zb = *(const float4*)(&sZb[q][ty * 4]);
            float wa0 = w * za.x, wa1 = w * za.y, wa2 = w * za.z, wa3 = w * za.w;
            C[0][0] = fmaf(wa0, zb.x, C[0][0]); C[0][1] = fmaf(wa0, zb.y, C[0][1]);
            C[0][2] = fmaf(wa0, zb.z, C[0][2]); C[0][3] = fmaf(wa0, zb.w, C[0][3]);
            C[1][0] = fmaf(wa1, zb.x, C[1][0]); C[1][1] = fmaf(wa1, zb.y, C[1][1]);
            C[1][2] = fmaf(wa1, zb.z, C[1][2]); C[1][3] = fmaf(wa1, zb.w, C[1][3]);
            C[2][0] = fmaf(wa2, zb.x, C[2][0]); C[2][1] = fmaf(wa2, zb.y, C[2][1]);
            C[2][2] = fmaf(wa2, zb.z, C[2][2]); C[2][3] = fmaf(wa2, zb.w, C[2][3]);
            C[3][0] = fmaf(wa3, zb.x, C[3][0]); C[3][1] = fmaf(wa3, zb.y, C[3][1]);
            C[3][2] = fmaf(wa3, zb.z, C[3][2]); C[3][3] = fmaf(wa3, zb.w, C[3][3]);
        }
        float fa[4], fb[4];
        #pragma unroll
        for (int i = 0; i < 4; i++) { fa[i] = sFa[tx*4 + i]; fb[i] = sFb[ty*4 + i]; }
        #pragma unroll
        for (int i = 0; i < 4; i++)
            #pragma unroll
            for (int j = 0; j < 4; j++)
                acc[i][j] = fmaf(fa[i] * fb[j], __expf(-0.5f * C[i][j]), acc[i][j]);
    }
    float* part = &g_part[(size_t)ch * MI * MI];
    #pragma unroll
    for (int i = 0; i < 4; i++) {
        int a = a0 + tx * 4 + i;
        #pragma unroll
        for (int j = 0; j < 4; j++) {
            int b = b0 + ty * 4 + j;
            part[a*MI + b] = acc[i][j];
        }
    }
}

// deterministic chunk reduction + symmetrization + pd scaling
__global__ void k_reduce_psi2() {
    int a = blockIdx.x, b = threadIdx.x;
    int ta = a >> 6, tb = b >> 6;
    int idx = (ta <= tb) ? (a * MI + b) : (b * MI + a);
    float s = 0.f;
    #pragma unroll
    for (int ch = 0; ch < NCHUNK; ch++) s += g_part[ch * MI * MI + idx];
    g_psi2[a*MI + b] = g_pd[a*MI + b] * s;
}

// ---------------- single-block Cholesky (packed lower in dyn smem), writes L^T ------
__global__ void __launch_bounds__(1024) k_chol(const float* __restrict__ Ain,
                                               float* __restrict__ LTout) {
    extern __shared__ float sL[];
    __shared__ float s_inv;
    int tid = threadIdx.x;
    for (int i = tid; i < MI * MI; i += 1024) {
        int r = i >> 8, c = i & 255;
        if (c <= r) sL[(r * (r + 1)) / 2 + c] = Ain[i];
    }
    __syncthreads();
    for (int k = 0; k < MI; k++) {
        int kk = (k * (k + 1)) / 2;
        if (tid == 0) {
            float v = sqrtf(sL[kk + k]);
            sL[kk + k] = v;
            s_inv = 1.f / v;
        }
        __syncthreads();
        for (int r = k + 1 + tid; r < MI; r += 1024)
            sL[(r * (r + 1)) / 2 + k] *= s_inv;
        __syncthreads();
        int i = k + 1 + (tid >> 2);
        if (i < MI) {
            int ib = (i * (i + 1)) / 2;
            float lik = sL[ib + k];
            for (int j = k + 1 + (tid & 3); j <= i; j += 4)
                sL[ib + j] -= lik * sL[(j * (j + 1)) / 2 + k];
        }
        __syncthreads();
    }
    for (int i = tid; i < MI * MI; i += 1024) {
        int m = i >> 8, r = i & 255;
        LTout[i] = (r >= m) ? sL[(r * (r + 1)) / 2 + m] : 0.f;
    }
}

// ---------------- forward TRSM: solve L X = B (32 cols / block), X *= scale ----------
__global__ void k_trsm(const float* __restrict__ LT, const float* __restrict__ B, int ldb,
                       float* __restrict__ X, int ldx, int ncols, float scale) {
    __shared__ float sx[256][33];
    __shared__ float sinv[256];
    int c0 = blockIdx.x * 32;
    int tid = threadIdx.x;
    sinv[tid] = 1.f / LT[tid * MI + tid];
    for (int i = tid; i < 256 * 32; i += 256) {
        int r = i >> 5, c = i & 31;
        sx[r][c] = (c0 + c < ncols) ? B[r * ldb + c0 + c] : 0.f;
    }
    __syncthreads();
    for (int m = 0; m < MI; m++) {
        if (tid < 32) sx[m][tid] *= sinv[m];
        __syncthreads();
        int r = m + 1 + tid;
        if (r < MI) {
            float l = LT[m * MI + r];
            #pragma unroll
            for (int c = 0; c < 32; c++) sx[r][c] -= l * sx[m][c];
        }
        __syncthreads();
    }
    for (int i = tid; i < 256 * 32; i += 256) {
        int r = i >> 5, c = i & 31;
        if (c0 + c < ncols) X[r * ldx + c0 + c] = sx[r][c] * scale;
    }
}

__global__ void k_transpose(const float* __restrict__ in, float* __restrict__ out) {
    int i = blockIdx.x * 256 + threadIdx.x;
    int r = i >> 8, c = i & 255;
    out[c * MI + r] = in[i];
}

__global__ void k_addI() {
    int i = blockIdx.x * 256 + threadIdx.x;
    int r = i >> 8, c = i & 255;
    g_Bm[i] = g_AAT[i] + ((r == c) ? 1.f : 0.f);
}

// ---------------- AY = A @ Y ----------------
__global__ void k_gemm_AY(const float* __restrict__ Y) {
    int m = blockIdx.x, tid = threadIdx.x;  // 128 threads
    float acc[DO] = {};
    for (int n = tid; n < NH; n += 128) {
        float a = g_A[m * NH + n];
        const float4* y4 = (const float4*)&Y[n * DO];
        #pragma unroll
        for (int d4 = 0; d4 < 4; d4++) {
            float4 y = y4[d4];
            acc[4*d4 + 0] = fmaf(a, y.x, acc[4*d4 + 0]);
            acc[4*d4 + 1] = fmaf(a, y.y, acc[4*d4 + 1]);
            acc[4*d4 + 2] = fmaf(a, y.z, acc[4*d4 + 2]);
            acc[4*d4 + 3] = fmaf(a, y.w, acc[4*d4 + 3]);
        }
    }
    __shared__ float sred[128];
    for (int d = 0; d < DO; d++) {
        sred[tid] = acc[d];
        __syncthreads();
        for (int s = 64; s > 0; s >>= 1) {
            if (tid < s) sred[tid] += sred[tid + s];
            __syncthreads();
        }
        if (tid == 0) g_AY[m * DO + d] = sred[0];
        __syncthreads();
    }
}

// ---------------- final bound assembly (double reductions) ----------------
__global__ void k_final(const float* __restrict__ Y, const float* __restrict__ kvp,
                        float* __restrict__ out) {
    int tid = threadIdx.x;  // 256
    double y2 = 0.0, c2 = 0.0, tr = 0.0, ld = 0.0;
    for (int i = tid; i < NH * DO; i += 256) { double y = Y[i]; y2 = fma(y, y, y2); }
    for (int i = tid; i < MI * DO; i += 256) { double v = g_cmat[i]; c2 = fma(v, v, c2); }
    if (tid < MI) {
        tr = (double)g_AAT[tid * MI + tid];
        ld = log((double)g_LBT[tid * MI + tid]);
    }
    __shared__ double sd[256];
    double vals[4] = { y2, c2, tr, ld };
    double res[4];
    for (int v = 0; v < 4; v++) {
        sd[tid] = vals[v];
        __syncthreads();
        for (int s = 128; s > 0; s >>= 1) {
            if (tid < s) sd[tid] += sd[tid + s];
            __syncthreads();
        }
        res[v] = sd[0];
        __syncthreads();
    }
    if (tid == 0) {
        double sigma2 = 1.0e-3;
        double kv = (double)(*kvp);
        double psi0 = (double)NH * kv;
        double bound = -0.5 * (double)NH * (double)DO * log(2.0 * M_PI * sigma2);
        bound -= 0.5 / sigma2 * res[0];                     // -0.5/s2 * sum Y^2
        bound -= 0.5 * (double)DO * (psi0 / sigma2 - res[2]); // psi0/trace term
        bound -= (double)DO * res[3];                       // -0.5*D*(2*sum log diag LB)
        bound += 0.5 * res[1];                              // +0.5 sum c^2
        out[0] = (float)bound;
    }
}

// ---------------- host launcher ----------------
extern "C" void kernel_launch(void* const* d_in, const int* in_sizes, int n_in,
                              void* d_out, int out_size) {
    const float* Xm = (const float*)d_in[0];
    const float* Xv = (const float*)d_in[1];
    const float* Z  = (const float*)d_in[2];
    const float* Y  = (const float*)d_in[3];
    const float* kv = (const float*)d_in[4];
    const float* ls = (const float*)d_in[5];
    float* out = (float*)d_out;

    float *pKuu, *pLT, *pPsi1T, *pA, *pPsi2, *pTmp, *pTmpT, *pAAT, *pBm, *pLBT, *pAY, *pC;
    cudaGetSymbolAddress((void**)&pKuu,   g_Kuu);
    cudaGetSymbolAddress((void**)&pLT,    g_LT);
    cudaGetSymbolAddress((void**)&pPsi1T, g_psi1T);
    cudaGetSymbolAddress((void**)&pA,     g_A);
    cudaGetSymbolAddress((void**)&pPsi2,  g_psi2);
    cudaGetSymbolAddress((void**)&pTmp,   g_tmp);
    cudaGetSymbolAddress((void**)&pTmpT,  g_tmpT);
    cudaGetSymbolAddress((void**)&pAAT,   g_AAT);
    cudaGetSymbolAddress((void**)&pBm,    g_Bm);
    cudaGetSymbolAddress((void**)&pLBT,   g_LBT);
    cudaGetSymbolAddress((void**)&pAY,    g_AY);
    cudaGetSymbolAddress((void**)&pC,     g_cmat);

    int cholSmem = (MI * (MI + 1) / 2) * (int)sizeof(float);  // 131,584 B
    cudaFuncSetAttribute(k_chol, cudaFuncAttributeMaxDynamicSharedMemorySize, cholSmem);

    const float inv_sigma  = 31.622776601683793f;  // 1/sqrt(1e-3)
    const float inv_sigma2 = 1000.0f;

    k_prep<<<NH, 128>>>(Xm, Xv, ls);
    k_kuu<<<dim3(16, 16), dim3(16, 16)>>>(Z, ls, kv);
    k_psi1F<<<dim3(16, 125), dim3(16, 16)>>>(Z, kv);
    k_psi2<<<dim3(10, NCHUNK), 256>>>(Z);
    k_reduce_psi2<<<256, 256>>>();
    k_chol<<<1, 1024, cholSmem>>>(pKuu, pLT);
    k_trsm<<<(NH + 31) / 32, 256>>>(pLT, pPsi1T, NH, pA, NH, NH, inv_sigma);
    k_trsm<<<8, 256>>>(pLT, pPsi2, MI, pTmp, MI, MI, 1.0f);
    k_transpose<<<256, 256>>>(pTmp, pTmpT);
    k_trsm<<<8, 256>>>(pLT, pTmpT, MI, pAAT, MI, MI, inv_sigma2);
    k_addI<<<256, 256>>>();
    k_chol<<<1, 1024, cholSmem>>>(pBm, pLBT);
    k_gemm_AY<<<MI, 128>>>(Y);
    k_trsm<<<1, 256>>>(pLBT, pAY, DO, pC, DO, DO, inv_sigma);
    k_final<<<1, 256>>>(Y, kv, out);
}

// round 3
// speedup vs baseline: 1.2368x; 1.2368x over previous
#include <cuda_runtime.h>
#include <math.h>

#define NTOT 2010
#define QD 8
#define LTW 10
#define DIN 80
#define NH 2000
#define MI 256
#define DO 16
#define NCHUNK 59
#define CHUNK 34
#define JITTERF 1.0e-4f

// ---------------- device scratch (static, no allocation) ----------------
__device__ float g_P[NH*DIN], g_R[NH*DIN], g_U[NH*DIN], g_W[NH*DIN];
__device__ float g_a1[NH], g_lc1[NH], g_h[NH];
__device__ float g_F[NH*MI];
__device__ float g_psi1T[MI*NH];
__device__ float g_Kuu[MI*MI];        // becomes L (lower) in place
__device__ float g_LT[MI*MI];         // L^T (upper), zeros below
__device__ float g_pd[MI*MI];
__device__ float g_part[NCHUNK*MI*MI];
__device__ float g_psi2[MI*MI];
__device__ float g_tmp[MI*MI];
__device__ float g_tmpT[MI*MI];
__device__ float g_AAT[MI*MI];
__device__ float g_Bm[MI*MI];         // becomes LB (lower) in place
__device__ float g_LBT[MI*MI];
__device__ float g_G[MI*DO];
__device__ float g_H[MI*DO];
__device__ float g_cmat[MI*DO];
__device__ float g_dinvA[MI], g_dinvB[MI];

__constant__ int c_ta[10] = {0,0,0,0,1,1,1,2,2,3};
__constant__ int c_tb[10] = {0,1,2,3,1,2,3,2,3,3};

// ---------------- per-n preprocessing (hankel + per-row stats) ----------------
__global__ void k_prep(const float* __restrict__ Xm, const float* __restrict__ Xv,
                       const float* __restrict__ ls) {
    int n = blockIdx.x, t = threadIdx.x;
    float4 v = make_float4(0.f, 0.f, 0.f, 0.f);
    if (t < DIN) {
        int l = t / QD, q = t - l * QD;
        float xm = Xm[(1 + n + l) * QD + q];
        float xv = Xv[(1 + n + l) * QD + q];
        float lsv = ls[t];
        float ls2 = lsv * lsv;
        float d1 = xv + ls2, d2 = 2.f * xv + ls2;
        float id1 = 1.f / d1, id2 = 1.f / d2;
        g_P[n*DIN + t] = xm * id1;
        g_R[n*DIN + t] = id1;
        g_U[n*DIN + t] = xm * id2;
        g_W[n*DIN + t] = id2;
        v.x = xm * xm * id1;
        v.y = log1pf(xv / ls2);
        v.z = xm * xm * id2;
        v.w = log1pf(2.f * xv / ls2);
    }
    __shared__ float4 sr[128];
    sr[t] = v;
    __syncthreads();
    for (int s = 64; s > 0; s >>= 1) {
        if (t < s) {
            float4 a = sr[t], b = sr[t + s];
            a.x += b.x; a.y += b.y; a.z += b.z; a.w += b.w;
            sr[t] = a;
        }
        __syncthreads();
    }
    if (t == 0) {
        float4 r = sr[0];
        g_a1[n]  = r.x;
        g_lc1[n] = -0.5f * r.y;
        g_h[n]   = -0.5f * r.w - r.z;   // logc2 - c2
    }
}

// ---------------- Kuu + kv^2*distfac ----------------
__global__ void k_kuu(const float* __restrict__ Z, const float* __restrict__ ls,
                      const float* __restrict__ kvp) {
    __shared__ float sZa[16][DIN+1], sZb[16][DIN+1], sil[DIN];
    int a0 = blockIdx.y * 16, b0 = blockIdx.x * 16;
    int tx = threadIdx.x, ty = threadIdx.y, tid = ty * 16 + tx;
    for (int i = tid; i < 16 * DIN; i += 256) {
        int r = i / DIN, q = i - r * DIN;
        sZa[r][q] = Z[(a0 + r) * DIN + q];
        sZb[r][q] = Z[(b0 + r) * DIN + q];
    }
    if (tid < DIN) { float L = ls[tid]; sil[tid] = 1.f / (L * L); }
    __syncthreads();
    float d2 = 0.f;
    #pragma unroll 16
    for (int q = 0; q < DIN; q++) {
        float d = sZa[ty][q] - sZb[tx][q];
        d2 = fmaf(d * d, sil[q], d2);
    }
    float kv = *kvp;
    int a = a0 + ty, b = b0 + tx;
    g_Kuu[a*MI + b] = kv * __expf(-0.5f * d2) + ((a == b) ? JITTERF : 0.f);
    g_pd[a*MI + b]  = kv * kv * __expf(-0.25f * d2);
}

// ---------------- psi1^T and F = exp(0.5h + t) ----------------
__global__ void k_psi1F(const float* __restrict__ Z, const float* __restrict__ kvp) {
    __shared__ float sZ[16][DIN+1], sZq[16][DIN+1];
    __shared__ float sP[16][DIN+1], sR[16][DIN+1], sU[16][DIN+1], sW[16][DIN+1];
    int m0 = blockIdx.x * 16, n0 = blockIdx.y * 16;
    int tx = threadIdx.x, ty = threadIdx.y, tid = ty * 16 + tx;
    for (int i = tid; i < 16 * DIN; i += 256) {
        int r = i / DIN, q = i - r * DIN;
        float z = Z[(m0 + r) * DIN + q];
        sZ[r][q] = z; sZq[r][q] = z * z;
        int ni = (n0 + r) * DIN + q;
        sP[r][q] = g_P[ni]; sR[r][q] = g_R[ni];
        sU[r][q] = g_U[ni]; sW[r][q] = g_W[ni];
    }
    __syncthreads();
    float pz = 0.f, rz = 0.f, uz = 0.f, wz = 0.f;
    #pragma unroll 8
    for (int q = 0; q < DIN; q++) {
        float z = sZ[tx][q], zq = sZq[tx][q];
        pz = fmaf(sP[ty][q], z,  pz);
        rz = fmaf(sR[ty][q], zq, rz);
        uz = fmaf(sU[ty][q], z,  uz);
        wz = fmaf(sW[ty][q], zq, wz);
    }
    int n = n0 + ty, m = m0 + tx;
    float kv = *kvp;
    g_psi1T[m*NH + n] = kv * __expf(fmaf(-0.5f, g_a1[n] - 2.f * pz + rz, g_lc1[n]));
    g_F[n*MI + m]     = __expf(0.5f * g_h[n] + uz - 0.25f * wz);
}

// ---------------- big psi2 kernel ----------------
__global__ void __launch_bounds__(256) k_psi2(const float* __restrict__ Z) {
    __shared__ __align__(16) float sZa[DIN][64];
    __shared__ __align__(16) float sZb[DIN][64];
    __shared__ float sW[DIN], sFa[64], sFb[64];
    int tp = blockIdx.x, ch = blockIdx.y;
    int a0 = c_ta[tp] * 64, b0 = c_tb[tp] * 64;
    int tid = threadIdx.x;
    for (int i = tid; i < 64 * DIN; i += 256) {
        int r = i & 63, q = i >> 6;
        sZa[q][r] = Z[(a0 + r) * DIN + q];
        sZb[q][r] = Z[(b0 + r) * DIN + q];
    }
    int tx = tid & 15, ty = tid >> 4;
    float acc[4][4] = {};
    int n0 = ch * CHUNK;
    int n1 = n0 + CHUNK; if (n1 > NH) n1 = NH;
    for (int n = n0; n < n1; n++) {
        __syncthreads();
        if (tid < DIN)                      sW[tid]        = g_W[n*DIN + tid];
        else if (tid >= 128 && tid < 192)   sFa[tid - 128] = g_F[n*MI + a0 + (tid - 128)];
        else if (tid >= 192)                sFb[tid - 192] = g_F[n*MI + b0 + (tid - 192)];
        __syncthreads();
        float C[4][4] = {};
        #pragma unroll 10
        for (int q = 0; q < DIN; q++) {
            float w = sW[q];
            float4 za = *(const float4*)(&sZa[q][tx * 4]);
            float4 zb = *(const float4*)(&sZb[q][ty * 4]);
            float wa0 = w * za.x, wa1 = w * za.y, wa2 = w * za.z, wa3 = w * za.w;
            C[0][0] = fmaf(wa0, zb.x, C[0][0]); C[0][1] = fmaf(wa0, zb.y, C[0][1]);
            C[0][2] = fmaf(wa0, zb.z, C[0][2]); C[0][3] = fmaf(wa0, zb.w, C[0][3]);
            C[1][0] = fmaf(wa1, zb.x, C[1][0]); C[1][1] = fmaf(wa1, zb.y, C[1][1]);
            C[1][2] = fmaf(wa1, zb.z, C[1][2]); C[1][3] = fmaf(wa1, zb.w, C[1][3]);
            C[2][0] = fmaf(wa2, zb.x, C[2][0]); C[2][1] = fmaf(wa2, zb.y, C[2][1]);
            C[2][2] = fmaf(wa2, zb.z, C[2][2]); C[2][3] = fmaf(wa2, zb.w, C[2][3]);
            C[3][0] = fmaf(wa3, zb.x, C[3][0]); C[3][1] = fmaf(wa3, zb.y, C[3][1]);
            C[3][2] = fmaf(wa3, zb.z, C[3][2]); C[3][3] = fmaf(wa3, zb.w, C[3][3]);
        }
        float fa[4], fb[4];
        #pragma unroll
        for (int i = 0; i < 4; i++) { fa[i] = sFa[tx*4 + i]; fb[i] = sFb[ty*4 + i]; }
        #pragma unroll
        for (int i = 0; i < 4; i++)
            #pragma unroll
            for (int j = 0; j < 4; j++)
                acc[i][j] = fmaf(fa[i] * fb[j], __expf(-0.5f * C[i][j]), acc[i][j]);
    }
    float* part = &g_part[(size_t)ch * MI * MI];
    #pragma unroll
    for (int i = 0; i < 4; i++) {
        int a = a0 + tx * 4 + i;
        #pragma unroll
        for (int j = 0; j < 4; j++) {
            int b = b0 + ty * 4 + j;
            part[a*MI + b] = acc[i][j];
        }
    }
}

// deterministic coalesced chunk reduction + symmetrization + pd scaling
__global__ void k_reduce_psi2() {
    int a = blockIdx.x, b = threadIdx.x;
    int ta = a >> 6, tb = b >> 6;
    if (ta > tb) return;       // covered by mirror write from (b,a)
    int idx = a * MI + b;
    float s = 0.f;
    #pragma unroll
    for (int ch = 0; ch < NCHUNK; ch++) s += g_part[ch * MI * MI + idx];
    float v = g_pd[idx] * s;
    g_psi2[idx] = v;
    if (ta < tb) g_psi2[b * MI + a] = v;
}

// ================= blocked Cholesky (64-wide, in-place lower, global mem) ======
__global__ void k_bchol_diag(float* __restrict__ A, int K) {
    __shared__ float s[64][65];
    __shared__ float sinv;
    int tid = threadIdx.x, base = K * 64;
    for (int i = tid; i < 64 * 64; i += 256) {
        int r = i >> 6, c = i & 63;
        s[r][c] = A[(base + r) * MI + base + c];
    }
    __syncthreads();
    for (int k = 0; k < 64; k++) {
        if (tid == 0) {
            float d = sqrtf(s[k][k]);
            s[k][k] = d;
            sinv = 1.f / d;
        }
        __syncthreads();
        if (tid > k && tid < 64) s[tid][k] *= sinv;
        __syncthreads();
        int tx = tid & 31, ty = tid >> 5;
        for (int r = k + 1 + ty; r < 64; r += 8) {
            float lr = s[r][k];
            for (int j = k + 1 + tx; j <= r; j += 32)
                s[r][j] -= lr * s[j][k];
        }
        __syncthreads();
    }
    for (int i = tid; i < 64 * 64; i += 256) {
        int r = i >> 6, c = i & 63;
        if (c <= r) A[(base + r) * MI + base + c] = s[r][c];
    }
}

// panel: rows below diag block solve L_KK * x = a  (warp-per-row, update form)
__global__ void k_bchol_panel(float* __restrict__ A, int K) {
    __shared__ float sLK[64][65];
    __shared__ float sdinv[64];
    int tid = threadIdx.x, lane = tid & 31, w = tid >> 5;
    int base = K * 64;
    for (int i = tid; i < 64 * 64; i += 256) {
        int r = i >> 6, c = i & 63;
        sLK[r][c] = A[(base + r) * MI + base + c];
    }
    __syncthreads();
    if (tid < 64) sdinv[tid] = 1.f / sLK[tid][tid];
    __syncthreads();
    int row = base + 64 + blockIdx.x * 8 + w;
    float x0 = A[row * MI + base + lane];
    float x1 = A[row * MI + base + 32 + lane];
    #pragma unroll 8
    for (int m = 0; m < 64; m++) {
        float src = (m < 32) ? x0 : x1;
        float v = __shfl_sync(0xffffffffu, src, m & 31);
        float xm = v * sdinv[m];
        if (lane == (m & 31)) { if (m < 32) x0 = xm; else x1 = xm; }
        if (lane > m)        x0 -= xm * sLK[lane][m];
        if (32 + lane > m)   x1 -= xm * sLK[32 + lane][m];
    }
    A[row * MI + base + lane]      = x0;
    A[row * MI + base + 32 + lane] = x1;
}

// trailing SYRK: A22 -= L21 * L21^T on 32x32 lower tiles
__global__ void k_bchol_trail(float* __restrict__ A, int K) {
    __shared__ float sP[32][65], sQ[32][65];
    int R0 = (K + 1) * 64, cb = K * 64;
    int t = blockIdx.x, ti = 0;
    while (t > ti) { t -= (ti + 1); ti++; }
    int tj = t;
    int gr = R0 + ti * 32, gc = R0 + tj * 32;
    int tid = threadIdx.x;
    for (int i = tid; i < 32 * 64; i += 256) {
        int r = i >> 6, c = i & 63;
        sP[r][c] = A[(gr + r) * MI + cb + c];
        sQ[r][c] = A[(gc + r) * MI + cb + c];
    }
    __syncthreads();
    int tx = tid & 31, ty = tid >> 5;
    int r0 = ty * 4;
    float a0 = 0.f, a1 = 0.f, a2 = 0.f, a3 = 0.f;
    #pragma unroll 16
    for (int k = 0; k < 64; k++) {
        float b = sQ[tx][k];
        a0 = fmaf(sP[r0][k],     b, a0);
        a1 = fmaf(sP[r0 + 1][k], b, a1);
        a2 = fmaf(sP[r0 + 2][k], b, a2);
        a3 = fmaf(sP[r0 + 3][k], b, a3);
    }
    A[(gr + r0) * MI + gc + tx]     -= a0;
    A[(gr + r0 + 1) * MI + gc + tx] -= a1;
    A[(gr + r0 + 2) * MI + gc + tx] -= a2;
    A[(gr + r0 + 3) * MI + gc + tx] -= a3;
}

// transpose lower L -> LT (upper), plus diag reciprocals
__global__ void k_transposeL(const float* __restrict__ in, float* __restrict__ out,
                             float* __restrict__ dinv) {
    int r = blockIdx.x, c = threadIdx.x;
    float v = in[r * MI + c];
    out[c * MI + r] = (c <= r) ? v : 0.f;
    if (c == r) dinv[r] = 1.f / v;
}

__global__ void k_transpose(const float* __restrict__ in, float* __restrict__ out) {
    int i = blockIdx.x * 256 + threadIdx.x;
    int r = i >> 8, c = i & 255;
    out[c * MI + r] = in[i];
}

// column-parallel forward solve: X = scale * L^{-1} B, one warp per column.
// LT is L^T (row-major upper) so the update reads rows coalesced.
__global__ void k_colsolveT(const float* __restrict__ LT, const float* __restrict__ dinv,
                            const float* __restrict__ B, int ldb,
                            float* __restrict__ X, int ldx, float scale) {
    __shared__ float sx[8][MI];
    int w = threadIdx.x >> 5, lane = threadIdx.x & 31;
    int col = blockIdx.x * 8 + w;
    float* x = sx[w];
    for (int j = lane; j < MI; j += 32) x[j] = B[j * ldb + col];
    __syncwarp();
    for (int m = 0; m < MI; m++) {
        float xm = x[m] * dinv[m];
        __syncwarp();
        if (lane == 0) x[m] = xm;
        const float* lrow = &LT[m * MI];
        for (int j = m + 1 + lane; j < MI; j += 32)
            x[j] -= xm * lrow[j];
        __syncwarp();
    }
    for (int j = lane; j < MI; j += 32) X[j * ldx + col] = x[j] * scale;
}

__global__ void k_addI() {
    int i = blockIdx.x * 256 + threadIdx.x;
    int r = i >> 8, c = i & 255;
    g_Bm[i] = g_AAT[i] + ((r == c) ? 1.f : 0.f);
}

// ---------------- G = psi1^T @ Y  [MI x DO] ----------------
__global__ void k_gemm_G(const float* __restrict__ Y) {
    int m = blockIdx.x, tid = threadIdx.x;  // 128 threads
    float acc[DO] = {};
    for (int n = tid; n < NH; n += 128) {
        float a = g_psi1T[m * NH + n];
        const float4* y4 = (const float4*)&Y[n * DO];
        #pragma unroll
        for (int d4 = 0; d4 < 4; d4++) {
            float4 y = y4[d4];
            acc[4*d4 + 0] = fmaf(a, y.x, acc[4*d4 + 0]);
            acc[4*d4 + 1] = fmaf(a, y.y, acc[4*d4 + 1]);
            acc[4*d4 + 2] = fmaf(a, y.z, acc[4*d4 + 2]);
            acc[4*d4 + 3] = fmaf(a, y.w, acc[4*d4 + 3]);
        }
    }
    __shared__ float sred[128];
    for (int d = 0; d < DO; d++) {
        sred[tid] = acc[d];
        __syncthreads();
        for (int s = 64; s > 0; s >>= 1) {
            if (tid < s) sred[tid] += sred[tid + s];
            __syncthreads();
        }
        if (tid == 0) g_G[m * DO + d] = sred[0];
        __syncthreads();
    }
}

// ---------------- final bound assembly (double reductions) ----------------
__global__ void k_final(const float* __restrict__ Y, const float* __restrict__ kvp,
                        float* __restrict__ out) {
    int tid = threadIdx.x;  // 256
    double y2 = 0.0, c2 = 0.0, tr = 0.0, ld = 0.0;
    for (int i = tid; i < NH * DO; i += 256) { double y = Y[i]; y2 = fma(y, y, y2); }
    for (int i = tid; i < MI * DO; i += 256) { double v = g_cmat[i]; c2 = fma(v, v, c2); }
    if (tid < MI) {
        tr = (double)g_AAT[tid * MI + tid];
        ld = log((double)g_Bm[tid * MI + tid]);   // diag of LB
    }
    __shared__ double sd[256];
    double vals[4] = { y2, c2, tr, ld };
    double res[4];
    for (int v = 0; v < 4; v++) {
        sd[tid] = vals[v];
        __syncthreads();
        for (int s = 128; s > 0; s >>= 1) {
            if (tid < s) sd[tid] += sd[tid + s];
            __syncthreads();
        }
        res[v] = sd[0];
        __syncthreads();
    }
    if (tid == 0) {
        double sigma2 = 1.0e-3;
        double kv = (double)(*kvp);
        double psi0 = (double)NH * kv;
        double bound = -0.5 * (double)NH * (double)DO * log(2.0 * M_PI * sigma2);
        bound -= 0.5 / sigma2 * res[0];
        bound -= 0.5 * (double)DO * (psi0 / sigma2 - res[2]);
        bound -= (double)DO * res[3];
        bound += 0.5 * res[1];
        out[0] = (float)bound;
    }
}

// ---------------- host launcher ----------------
static void launch_chol(float* A) {
    for (int K = 0; K < 4; K++) {
        k_bchol_diag<<<1, 256>>>(A, K);
        int rows = MI - (K + 1) * 64;
        if (rows > 0) {
            k_bchol_panel<<<rows / 8, 256>>>(A, K);
            int nt = rows / 32;
            k_bchol_trail<<<nt * (nt + 1) / 2, 256>>>(A, K);
        }
    }
}

extern "C" void kernel_launch(void* const* d_in, const int* in_sizes, int n_in,
                              void* d_out, int out_size) {
    const float* Xm = (const float*)d_in[0];
    const float* Xv = (const float*)d_in[1];
    const float* Z  = (const float*)d_in[2];
    const float* Y  = (const float*)d_in[3];
    const float* kv = (const float*)d_in[4];
    const float* ls = (const float*)d_in[5];
    float* out = (float*)d_out;

    float *pKuu, *pLT, *pPsi2, *pTmp, *pTmpT, *pAAT, *pBm, *pLBT, *pG, *pH, *pC, *pDA, *pDB;
    cudaGetSymbolAddress((void**)&pKuu,  g_Kuu);
    cudaGetSymbolAddress((void**)&pLT,   g_LT);
    cudaGetSymbolAddress((void**)&pPsi2, g_psi2);
    cudaGetSymbolAddress((void**)&pTmp,  g_tmp);
    cudaGetSymbolAddress((void**)&pTmpT, g_tmpT);
    cudaGetSymbolAddress((void**)&pAAT,  g_AAT);
    cudaGetSymbolAddress((void**)&pBm,   g_Bm);
    cudaGetSymbolAddress((void**)&pLBT,  g_LBT);
    cudaGetSymbolAddress((void**)&pG,    g_G);
    cudaGetSymbolAddress((void**)&pH,    g_H);
    cudaGetSymbolAddress((void**)&pC,    g_cmat);
    cudaGetSymbolAddress((void**)&pDA,   g_dinvA);
    cudaGetSymbolAddress((void**)&pDB,   g_dinvB);

    const float inv_sigma2 = 1000.0f;   // 1/sigma^2

    k_prep<<<NH, 128>>>(Xm, Xv, ls);
    k_kuu<<<dim3(16, 16), dim3(16, 16)>>>(Z, ls, kv);
    k_psi1F<<<dim3(16, 125), dim3(16, 16)>>>(Z, kv);
    k_psi2<<<dim3(10, NCHUNK), 256>>>(Z);
    k_reduce_psi2<<<256, 256>>>();

    // chol(Kuu) in place -> L in g_Kuu lower
    launch_chol(pKuu);
    k_transposeL<<<256, 256>>>(pKuu, pLT, pDA);

    // AAT = L^{-1} psi2 L^{-T} / sigma2
    k_colsolveT<<<32, 256>>>(pLT, pDA, pPsi2, MI, pTmp, MI, 1.0f);
    k_transpose<<<256, 256>>>(pTmp, pTmpT);
    k_colsolveT<<<32, 256>>>(pLT, pDA, pTmpT, MI, pAAT, MI, inv_sigma2);

    // B = AAT + I ; chol(B) -> LB in g_Bm lower
    k_addI<<<256, 256>>>();
    launch_chol(pBm);
    k_transposeL<<<256, 256>>>(pBm, pLBT, pDB);

    // c = LB^{-1} L^{-1} (psi1^T Y) / sigma^2
    k_gemm_G<<<MI, 128>>>(Y);
    k_colsolveT<<<2, 256>>>(pLT, pDA, pG, DO, pH, DO, 1.0f);
    k_colsolveT<<<2, 256>>>(pLBT, pDB, pH, DO, pC, DO, inv_sigma2);

    k_final<<<1, 256>>>(Y, kv, out);
}

// round 4
// speedup vs baseline: 1.8464x; 1.4929x over previous
#include <cuda_runtime.h>
#include <math.h>

#define NTOT 2010
#define QD 8
#define LTW 10
#define DIN 80
#define NH 2000
#define MI 256
#define DO 16
#define NCHUNK 44
#define CHUNK 46
#define JITTERF 1.0e-4f
#define PACKED 32896   // 256*257/2

// ---------------- device scratch (static, no allocation) ----------------
__device__ float g_P[NH*DIN], g_R[NH*DIN], g_U[NH*DIN], g_W[NH*DIN];
__device__ float g_a1[NH], g_lc1[NH], g_h[NH];
__device__ float g_F[NH*MI];
__device__ float g_psi1T[MI*NH];
__device__ float g_Kuu[MI*MI];
__device__ float g_pd[MI*MI];
__device__ float g_part[NCHUNK*MI*MI];
__device__ float g_psi2[MI*MI];
__device__ float g_Lp[PACKED];
__device__ float g_LBp[PACKED];
__device__ float g_dinvA[MI], g_dinvB[MI];
__device__ float g_tmp[MI*MI];
__device__ float g_AAT[MI*MI];
__device__ float g_G[MI*DO];
__device__ float g_H[MI*DO];
__device__ float g_cmat[MI*DO];

__constant__ int c_ta[10] = {0,0,0,0,1,1,1,2,2,3};
__constant__ int c_tb[10] = {0,1,2,3,1,2,3,2,3,3};

// ---------------- per-n preprocessing ----------------
__global__ void k_prep(const float* __restrict__ Xm, const float* __restrict__ Xv,
                       const float* __restrict__ ls) {
    int n = blockIdx.x, t = threadIdx.x;
    float4 v = make_float4(0.f, 0.f, 0.f, 0.f);
    if (t < DIN) {
        int l = t / QD, q = t - l * QD;
        float xm = Xm[(1 + n + l) * QD + q];
        float xv = Xv[(1 + n + l) * QD + q];
        float lsv = ls[t];
        float ls2 = lsv * lsv;
        float d1 = xv + ls2, d2 = 2.f * xv + ls2;
        float id1 = 1.f / d1, id2 = 1.f / d2;
        g_P[n*DIN + t] = xm * id1;
        g_R[n*DIN + t] = id1;
        g_U[n*DIN + t] = xm * id2;
        g_W[n*DIN + t] = id2;
        v.x = xm * xm * id1;
        v.y = log1pf(xv / ls2);
        v.z = xm * xm * id2;
        v.w = log1pf(2.f * xv / ls2);
    }
    __shared__ float4 sr[128];
    sr[t] = v;
    __syncthreads();
    for (int s = 64; s > 0; s >>= 1) {
        if (t < s) {
            float4 a = sr[t], b = sr[t + s];
            a.x += b.x; a.y += b.y; a.z += b.z; a.w += b.w;
            sr[t] = a;
        }
        __syncthreads();
    }
    if (t == 0) {
        float4 r = sr[0];
        g_a1[n]  = r.x;
        g_lc1[n] = -0.5f * r.y;
        g_h[n]   = -0.5f * r.w - r.z;
    }
}

// ---------------- Kuu + kv^2*distfac ----------------
__global__ void k_kuu(const float* __restrict__ Z, const float* __restrict__ ls,
                      const float* __restrict__ kvp) {
    __shared__ float sZa[16][DIN+1], sZb[16][DIN+1], sil[DIN];
    int a0 = blockIdx.y * 16, b0 = blockIdx.x * 16;
    int tx = threadIdx.x, ty = threadIdx.y, tid = ty * 16 + tx;
    for (int i = tid; i < 16 * DIN; i += 256) {
        int r = i / DIN, q = i - r * DIN;
        sZa[r][q] = Z[(a0 + r) * DIN + q];
        sZb[r][q] = Z[(b0 + r) * DIN + q];
    }
    if (tid < DIN) { float L = ls[tid]; sil[tid] = 1.f / (L * L); }
    __syncthreads();
    float d2 = 0.f;
    #pragma unroll 16
    for (int q = 0; q < DIN; q++) {
        float d = sZa[ty][q] - sZb[tx][q];
        d2 = fmaf(d * d, sil[q], d2);
    }
    float kv = *kvp;
    int a = a0 + ty, b = b0 + tx;
    g_Kuu[a*MI + b] = kv * __expf(-0.5f * d2) + ((a == b) ? JITTERF : 0.f);
    g_pd[a*MI + b]  = kv * kv * __expf(-0.25f * d2);
}

// ---------------- psi1^T and F ----------------
__global__ void k_psi1F(const float* __restrict__ Z, const float* __restrict__ kvp) {
    __shared__ float sZ[16][DIN+1], sZq[16][DIN+1];
    __shared__ float sP[16][DIN+1], sR[16][DIN+1], sU[16][DIN+1], sW[16][DIN+1];
    int m0 = blockIdx.x * 16, n0 = blockIdx.y * 16;
    int tx = threadIdx.x, ty = threadIdx.y, tid = ty * 16 + tx;
    for (int i = tid; i < 16 * DIN; i += 256) {
        int r = i / DIN, q = i - r * DIN;
        float z = Z[(m0 + r) * DIN + q];
        sZ[r][q] = z; sZq[r][q] = z * z;
        int ni = (n0 + r) * DIN + q;
        sP[r][q] = g_P[ni]; sR[r][q] = g_R[ni];
        sU[r][q] = g_U[ni]; sW[r][q] = g_W[ni];
    }
    __syncthreads();
    float pz = 0.f, rz = 0.f, uz = 0.f, wz = 0.f;
    #pragma unroll 8
    for (int q = 0; q < DIN; q++) {
        float z = sZ[tx][q], zq = sZq[tx][q];
        pz = fmaf(sP[ty][q], z,  pz);
        rz = fmaf(sR[ty][q], zq, rz);
        uz = fmaf(sU[ty][q], z,  uz);
        wz = fmaf(sW[ty][q], zq, wz);
    }
    int n = n0 + ty, m = m0 + tx;
    float kv = *kvp;
    g_psi1T[m*NH + n] = kv * __expf(fmaf(-0.5f, g_a1[n] - 2.f * pz + rz, g_lc1[n]));
    g_F[n*MI + m]     = __expf(0.5f * g_h[n] + uz - 0.25f * wz);
}

// ---------------- big psi2 kernel (dyn smem, staged -0.5*W*Za) ----------------
__global__ void __launch_bounds__(256) k_psi2(const float* __restrict__ Z) {
    extern __shared__ float dsm[];
    float* sZa = dsm;                 // DIN*64
    float* sZb = sZa + DIN*64;        // DIN*64
    float* sWZ = sZb + DIN*64;        // DIN*64
    float* sW  = sWZ + DIN*64;        // DIN
    float* sFa = sW + DIN;            // 64
    float* sFb = sFa + 64;            // 64
    int tp = blockIdx.x, ch = blockIdx.y;
    int a0 = c_ta[tp] * 64, b0 = c_tb[tp] * 64;
    int tid = threadIdx.x;
    for (int i = tid; i < 64 * DIN; i += 256) {
        int r = i & 63, q = i >> 6;
        sZa[q*64 + r] = Z[(a0 + r) * DIN + q];
        sZb[q*64 + r] = Z[(b0 + r) * DIN + q];
    }
    int tx = tid & 15, ty = tid >> 4;
    float acc[4][4] = {};
    int n0 = ch * CHUNK;
    int n1 = n0 + CHUNK; if (n1 > NH) n1 = NH;
    for (int n = n0; n < n1; n++) {
        __syncthreads();
        if (tid < DIN)                      sW[tid]        = g_W[n*DIN + tid];
        else if (tid >= 128 && tid < 192)   sFa[tid - 128] = g_F[n*MI + a0 + (tid - 128)];
        else if (tid >= 192)                sFb[tid - 192] = g_F[n*MI + b0 + (tid - 192)];
        __syncthreads();
        for (int i = tid; i < 64 * DIN; i += 256)
            sWZ[i] = -0.5f * sW[i >> 6] * sZa[i];
        __syncthreads();
        float C[4][4] = {};
        #pragma unroll 10
        for (int q = 0; q < DIN; q++) {
            float4 wa = *(const float4*)&sWZ[q*64 + tx*4];
            float4 zb = *(const float4*)&sZb[q*64 + ty*4];
            C[0][0] = fmaf(wa.x, zb.x, C[0][0]); C[0][1] = fmaf(wa.x, zb.y, C[0][1]);
            C[0][2] = fmaf(wa.x, zb.z, C[0][2]); C[0][3] = fmaf(wa.x, zb.w, C[0][3]);
            C[1][0] = fmaf(wa.y, zb.x, C[1][0]); C[1][1] = fmaf(wa.y, zb.y, C[1][1]);
            C[1][2] = fmaf(wa.y, zb.z, C[1][2]); C[1][3] = fmaf(wa.y, zb.w, C[1][3]);
            C[2][0] = fmaf(wa.z, zb.x, C[2][0]); C[2][1] = fmaf(wa.z, zb.y, C[2][1]);
            C[2][2] = fmaf(wa.z, zb.z, C[2][2]); C[2][3] = fmaf(wa.z, zb.w, C[2][3]);
            C[3][0] = fmaf(wa.w, zb.x, C[3][0]); C[3][1] = fmaf(wa.w, zb.y, C[3][1]);
            C[3][2] = fmaf(wa.w, zb.z, C[3][2]); C[3][3] = fmaf(wa.w, zb.w, C[3][3]);
        }
        float fa[4], fb[4];
        #pragma unroll
        for (int i = 0; i < 4; i++) { fa[i] = sFa[tx*4 + i]; fb[i] = sFb[ty*4 + i]; }
        #pragma unroll
        for (int i = 0; i < 4; i++)
            #pragma unroll
            for (int j = 0; j < 4; j++)
                acc[i][j] = fmaf(fa[i] * fb[j], __expf(C[i][j]), acc[i][j]);
    }
    float* part = &g_part[(size_t)ch * MI * MI];
    #pragma unroll
    for (int i = 0; i < 4; i++) {
        int a = a0 + tx * 4 + i;
        #pragma unroll
        for (int j = 0; j < 4; j++) {
            int b = b0 + ty * 4 + j;
            part[a*MI + b] = acc[i][j];
        }
    }
}

// deterministic chunk reduction + symmetrization + pd scaling
__global__ void k_reduce_psi2() {
    int a = blockIdx.x, b = threadIdx.x;
    int ta = a >> 6, tb = b >> 6;
    if (ta > tb) return;
    int idx = a * MI + b;
    float s = 0.f;
    #pragma unroll
    for (int ch = 0; ch < NCHUNK; ch++) s += g_part[ch * MI * MI + idx];
    float v = g_pd[idx] * s;
    g_psi2[idx] = v;
    if (ta < tb) g_psi2[b * MI + a] = v;
}

// ============ whole-256 Cholesky in one launch (packed lower in SMEM) ==========
// A row-major 256x256 (+optional I); outputs packed L and diag reciprocals.
__global__ void __launch_bounds__(1024) k_chol256(const float* __restrict__ A,
                                                  float* __restrict__ Lp,
                                                  float* __restrict__ dinv,
                                                  int addI) {
    extern __shared__ float sm[];
    float* sL  = sm;                 // PACKED
    float* sD  = sm + PACKED;        // 64*65
    float* sdi = sD + 64*65;         // 256
    int tid = threadIdx.x, lane = tid & 31, wid = tid >> 5;

    { // load packed lower (+ optional I)
        int r = tid >> 2, sub = tid & 3;
        int Pr = (r * (r + 1)) >> 1;
        for (int c = sub; c <= r; c += 4)
            sL[Pr + c] = A[r * MI + c] + ((addI && c == r) ? 1.f : 0.f);
    }
    __syncthreads();

    for (int K = 0; K < 4; K++) {
        int base = K * 64;
        // copy diag block -> sD (64x65)
        for (int i = tid; i < 64 * 64; i += 1024) {
            int r = i >> 6, c = i & 63;
            if (c <= r) sD[r*65 + c] = sL[(((base+r)*(base+r+1))>>1) + base + c];
        }
        __syncthreads();
        // warp 0 factors the 64x64 block
        if (wid == 0) {
            for (int k = 0; k < 64; k++) {
                if (lane == 0) {
                    float d = sqrtf(sD[k*65 + k]);
                    sD[k*65 + k] = d;
                    sdi[base + k] = 1.f / d;
                }
                __syncwarp();
                float inv = sdi[base + k];
                int r1 = lane + 32;
                if (lane > k) sD[lane*65 + k] *= inv;
                if (r1 > k)   sD[r1*65 + k]   *= inv;
                __syncwarp();
                float l0 = (lane > k) ? sD[lane*65 + k] : 0.f;
                float l1 = (r1 > k)   ? sD[r1*65 + k]   : 0.f;
                for (int j = k + 1; j <= lane; j++) sD[lane*65 + j] -= l0 * sD[j*65 + k];
                if (r1 > k)
                    for (int j = k + 1; j <= r1; j++) sD[r1*65 + j] -= l1 * sD[j*65 + k];
                __syncwarp();
            }
        }
        __syncthreads();
        // write factored diag back to packed
        for (int i = tid; i < 64 * 64; i += 1024) {
            int r = i >> 6, c = i & 63;
            if (c <= r) sL[(((base+r)*(base+r+1))>>1) + base + c] = sD[r*65 + c];
        }
        __syncthreads();
        int R = MI - base - 64;
        if (R > 0) {
            // panel: warp-per-row shuffle substitution vs sD
            for (int rr = wid; rr < R; rr += 32) {
                int row = base + 64 + rr;
                int Pr = (row * (row + 1)) >> 1;
                float x0 = sL[Pr + base + lane];
                float x1 = sL[Pr + base + 32 + lane];
                #pragma unroll
                for (int m = 0; m < 64; m++) {
                    float src = (m < 32) ? x0 : x1;
                    float v = __shfl_sync(0xffffffffu, src, m & 31);
                    float xm = v * sdi[base + m];
                    if (m < 32) {
                        if (lane == m) x0 = xm;
                        if (lane > m)  x0 -= xm * sD[lane*65 + m];
                        x1 -= xm * sD[(lane+32)*65 + m];
                    } else {
                        if (lane == m - 32) x1 = xm;
                        if (lane + 32 > m)  x1 -= xm * sD[(lane+32)*65 + m];
                    }
                }
                sL[Pr + base + lane]      = x0;
                sL[Pr + base + 32 + lane] = x1;
            }
            __syncthreads();
            // trailing SYRK: 32x32 tiles, 64 threads/tile, 4x4 micro
            int T = R >> 5;
            int ntiles = (T * (T + 1)) >> 1;
            int g = tid >> 6, gt = tid & 63;
            int tx = gt & 7, ty = gt >> 3;
            for (int tile = g; tile < ntiles; tile += 16) {
                int ti = 0, rem = tile;
                while (rem > ti) { rem -= (ti + 1); ti++; }
                int tj = rem;
                int gr = base + 64 + ti * 32, gc = base + 64 + tj * 32;
                int Pr[4], Pc[4];
                #pragma unroll
                for (int i = 0; i < 4; i++) { int r = gr + ty*4 + i; Pr[i] = ((r*(r+1))>>1) + base; }
                #pragma unroll
                for (int j = 0; j < 4; j++) { int c = gc + tx*4 + j; Pc[j] = ((c*(c+1))>>1) + base; }
                float acc[4][4] = {};
                #pragma unroll 16
                for (int k = 0; k < 64; k++) {
                    float la[4], lb[4];
                    #pragma unroll
                    for (int i = 0; i < 4; i++) la[i] = sL[Pr[i] + k];
                    #pragma unroll
                    for (int j = 0; j < 4; j++) lb[j] = sL[Pc[j] + k];
                    #pragma unroll
                    for (int i = 0; i < 4; i++)
                        #pragma unroll
                        for (int j = 0; j < 4; j++)
                            acc[i][j] = fmaf(la[i], lb[j], acc[i][j]);
                }
                #pragma unroll
                for (int i = 0; i < 4; i++) {
                    int r = gr + ty*4 + i;
                    int Prow = (r * (r + 1)) >> 1;
                    #pragma unroll
                    for (int j = 0; j < 4; j++) {
                        int c = gc + tx*4 + j;
                        if (c <= r) sL[Prow + c] -= acc[i][j];
                    }
                }
            }
        }
        __syncthreads();
    }
    { // store packed L + dinv
        int r = tid >> 2, sub = tid & 3;
        int Pr = (r * (r + 1)) >> 1;
        for (int c = sub; c <= r; c += 4) Lp[Pr + c] = sL[Pr + c];
    }
    if (tid < MI) dinv[tid] = sdi[tid];
}

// ============ register-resident column solve: X = scale * L^{-1} B ============
// Packed L staged in SMEM once per block; warp per column; x[8] in registers.
__global__ void __launch_bounds__(256) k_colsolve(const float* __restrict__ Lp,
                                                  const float* __restrict__ dinv,
                                                  const float* __restrict__ B, int ldb,
                                                  int transB,
                                                  float* __restrict__ X, int ldx,
                                                  float scale) {
    extern __shared__ float sm[];
    float* sLp = sm;              // PACKED
    float* sdi = sm + PACKED;     // 256
    int tid = threadIdx.x, lane = tid & 31, wid = tid >> 5;
    for (int i = tid; i < PACKED; i += 256) sLp[i] = Lp[i];
    if (tid < MI) sdi[tid] = dinv[tid];
    __syncthreads();

    int col = blockIdx.x * 8 + wid;
    float x[8];
    int Pt[8];
    #pragma unroll
    for (int t = 0; t < 8; t++) {
        int j = lane + 32 * t;
        Pt[t] = (j * (j + 1)) >> 1;
        x[t] = transB ? B[col * ldb + j] : B[j * ldb + col];
    }
    #pragma unroll
    for (int s = 0; s < 8; s++) {
        #pragma unroll
        for (int mm = 0; mm < 32; mm++) {
            int m = s * 32 + mm;
            float xm = __shfl_sync(0xffffffffu, x[s], mm) * sdi[m];
            if (lane == mm) x[s] = xm;
            if (lane > mm)  x[s] -= xm * sLp[Pt[s] + m];
            #pragma unroll
            for (int t = s + 1; t < 8; t++)
                x[t] -= xm * sLp[Pt[t] + m];
        }
    }
    #pragma unroll
    for (int t = 0; t < 8; t++)
        X[(lane + 32 * t) * ldx + col] = x[t] * scale;
}

// ---------------- G = psi1^T @ Y  [MI x DO] ----------------
__global__ void k_gemm_G(const float* __restrict__ Y) {
    int m = blockIdx.x, tid = threadIdx.x;  // 128 threads
    float acc[DO] = {};
    for (int n = tid; n < NH; n += 128) {
        float a = g_psi1T[m * NH + n];
        const float4* y4 = (const float4*)&Y[n * DO];
        #pragma unroll
        for (int d4 = 0; d4 < 4; d4++) {
            float4 y = y4[d4];
            acc[4*d4 + 0] = fmaf(a, y.x, acc[4*d4 + 0]);
            acc[4*d4 + 1] = fmaf(a, y.y, acc[4*d4 + 1]);
            acc[4*d4 + 2] = fmaf(a, y.z, acc[4*d4 + 2]);
            acc[4*d4 + 3] = fmaf(a, y.w, acc[4*d4 + 3]);
        }
    }
    __shared__ float sred[128];
    for (int d = 0; d < DO; d++) {
        sred[tid] = acc[d];
        __syncthreads();
        for (int s = 64; s > 0; s >>= 1) {
            if (tid < s) sred[tid] += sred[tid + s];
            __syncthreads();
        }
        if (tid == 0) g_G[m * DO + d] = sred[0];
        __syncthreads();
    }
}

// ---------------- final bound assembly (double reductions) ----------------
__global__ void k_final(const float* __restrict__ Y, const float* __restrict__ kvp,
                        float* __restrict__ out) {
    int tid = threadIdx.x;  // 256
    double y2 = 0.0, c2 = 0.0, tr = 0.0, ld = 0.0;
    for (int i = tid; i < NH * DO; i += 256) { double y = Y[i]; y2 = fma(y, y, y2); }
    for (int i = tid; i < MI * DO; i += 256) { double v = g_cmat[i]; c2 = fma(v, v, c2); }
    if (tid < MI) {
        tr = (double)g_AAT[tid * MI + tid];
        ld = -log((double)g_dinvB[tid]);   // log(diag LB)
    }
    __shared__ double sd[256];
    double vals[4] = { y2, c2, tr, ld };
    double res[4];
    for (int v = 0; v < 4; v++) {
        sd[tid] = vals[v];
        __syncthreads();
        for (int s = 128; s > 0; s >>= 1) {
            if (tid < s) sd[tid] += sd[tid + s];
            __syncthreads();
        }
        res[v] = sd[0];
        __syncthreads();
    }
    if (tid == 0) {
        double sigma2 = 1.0e-3;
        double kv = (double)(*kvp);
        double psi0 = (double)NH * kv;
        double bound = -0.5 * (double)NH * (double)DO * log(2.0 * M_PI * sigma2);
        bound -= 0.5 / sigma2 * res[0];
        bound -= 0.5 * (double)DO * (psi0 / sigma2 - res[2]);
        bound -= (double)DO * res[3];
        bound += 0.5 * res[1];
        out[0] = (float)bound;
    }
}

// ---------------- host launcher ----------------
extern "C" void kernel_launch(void* const* d_in, const int* in_sizes, int n_in,
                              void* d_out, int out_size) {
    const float* Xm = (const float*)d_in[0];
    const float* Xv = (const float*)d_in[1];
    const float* Z  = (const float*)d_in[2];
    const float* Y  = (const float*)d_in[3];
    const float* kv = (const float*)d_in[4];
    const float* ls = (const float*)d_in[5];
    float* out = (float*)d_out;

    float *pKuu, *pPsi2, *pLp, *pLBp, *pDA, *pDB, *pTmp, *pAAT, *pG, *pH, *pC;
    cudaGetSymbolAddress((void**)&pKuu,  g_Kuu);
    cudaGetSymbolAddress((void**)&pPsi2, g_psi2);
    cudaGetSymbolAddress((void**)&pLp,   g_Lp);
    cudaGetSymbolAddress((void**)&pLBp,  g_LBp);
    cudaGetSymbolAddress((void**)&pDA,   g_dinvA);
    cudaGetSymbolAddress((void**)&pDB,   g_dinvB);
    cudaGetSymbolAddress((void**)&pTmp,  g_tmp);
    cudaGetSymbolAddress((void**)&pAAT,  g_AAT);
    cudaGetSymbolAddress((void**)&pG,    g_G);
    cudaGetSymbolAddress((void**)&pH,    g_H);
    cudaGetSymbolAddress((void**)&pC,    g_cmat);

    const int PSI2_SMEM = (3 * DIN * 64 + DIN + 128) * (int)sizeof(float);      // 62,272
    const int CHOL_SMEM = (PACKED + 64*65 + 256) * (int)sizeof(float);          // 149,248
    const int SOLVE_SMEM = (PACKED + 256) * (int)sizeof(float);                 // 132,608
    cudaFuncSetAttribute(k_psi2,     cudaFuncAttributeMaxDynamicSharedMemorySize, PSI2_SMEM);
    cudaFuncSetAttribute(k_chol256,  cudaFuncAttributeMaxDynamicSharedMemorySize, CHOL_SMEM);
    cudaFuncSetAttribute(k_colsolve, cudaFuncAttributeMaxDynamicSharedMemorySize, SOLVE_SMEM);

    const float inv_sigma2 = 1000.0f;   // 1/sigma^2

    k_prep<<<NH, 128>>>(Xm, Xv, ls);
    k_kuu<<<dim3(16, 16), dim3(16, 16)>>>(Z, ls, kv);
    k_psi1F<<<dim3(16, 125), dim3(16, 16)>>>(Z, kv);
    k_psi2<<<dim3(10, NCHUNK), 256, PSI2_SMEM>>>(Z);
    k_reduce_psi2<<<256, 256>>>();

    // chol(Kuu) -> packed L, dinvA
    k_chol256<<<1, 1024, CHOL_SMEM>>>(pKuu, pLp, pDA, 0);

    // AAT = L^{-1} psi2 L^{-T} / sigma2   (psi2 symmetric -> transB reads)
    k_colsolve<<<32, 256, SOLVE_SMEM>>>(pLp, pDA, pPsi2, MI, 1, pTmp, MI, 1.0f);
    k_colsolve<<<32, 256, SOLVE_SMEM>>>(pLp, pDA, pTmp,  MI, 1, pAAT, MI, inv_sigma2);

    // chol(AAT + I) -> packed LB, dinvB  (I folded into load)
    k_chol256<<<1, 1024, CHOL_SMEM>>>(pAAT, pLBp, pDB, 1);

    // c = LB^{-1} L^{-1} (psi1^T Y) / sigma^2
    k_gemm_G<<<MI, 128>>>(Y);
    k_colsolve<<<2, 256, SOLVE_SMEM>>>(pLp,  pDA, pG, DO, 0, pH, DO, 1.0f);
    k_colsolve<<<2, 256, SOLVE_SMEM>>>(pLBp, pDB, pH, DO, 0, pC, DO, inv_sigma2);

    k_final<<<1, 256>>>(Y, kv, out);
}

// round 5
// speedup vs baseline: 2.6892x; 1.4564x over previous
#include <cuda_runtime.h>
#include <math.h>

#define NTOT 2010
#define QD 8
#define LTW 10
#define DIN 80
#define NH 2000
#define MI 256
#define DO 16
#define NCHUNK 44
#define CHUNK 46
#define JITTERF 1.0e-4f
#define PACKED 32896   // 256*257/2

// ---------------- device scratch (static, no allocation) ----------------
__device__ float g_P[NH*DIN], g_R[NH*DIN], g_U[NH*DIN], g_W[NH*DIN];
__device__ float g_a1[NH], g_lc1[NH], g_h[NH];
__device__ float g_F[NH*MI];
__device__ float g_psi1T[MI*NH];
__device__ float g_Kuu[MI*MI];
__device__ float g_pd[MI*MI];
__device__ float g_part[NCHUNK*MI*MI];
__device__ float g_psi2[MI*MI];
__device__ float g_Lp[PACKED];
__device__ float g_dinvA[MI];
__device__ float g_tmp[MI*MI];
__device__ float g_AAT[MI*MI];
__device__ float g_G[MI*DO];
__device__ float g_H[MI*DO];

__constant__ int c_ta[10] = {0,0,0,0,1,1,1,2,2,3};
__constant__ int c_tb[10] = {0,1,2,3,1,2,3,2,3,3};

// ---------------- per-n preprocessing ----------------
__global__ void k_prep(const float* __restrict__ Xm, const float* __restrict__ Xv,
                       const float* __restrict__ ls) {
    int n = blockIdx.x, t = threadIdx.x;
    float4 v = make_float4(0.f, 0.f, 0.f, 0.f);
    if (t < DIN) {
        int l = t / QD, q = t - l * QD;
        float xm = Xm[(1 + n + l) * QD + q];
        float xv = Xv[(1 + n + l) * QD + q];
        float lsv = ls[t];
        float ls2 = lsv * lsv;
        float d1 = xv + ls2, d2 = 2.f * xv + ls2;
        float id1 = 1.f / d1, id2 = 1.f / d2;
        g_P[n*DIN + t] = xm * id1;
        g_R[n*DIN + t] = id1;
        g_U[n*DIN + t] = xm * id2;
        g_W[n*DIN + t] = id2;
        v.x = xm * xm * id1;
        v.y = log1pf(xv / ls2);
        v.z = xm * xm * id2;
        v.w = log1pf(2.f * xv / ls2);
    }
    __shared__ float4 sr[128];
    sr[t] = v;
    __syncthreads();
    for (int s = 64; s > 0; s >>= 1) {
        if (t < s) {
            float4 a = sr[t], b = sr[t + s];
            a.x += b.x; a.y += b.y; a.z += b.z; a.w += b.w;
            sr[t] = a;
        }
        __syncthreads();
    }
    if (t == 0) {
        float4 r = sr[0];
        g_a1[n]  = r.x;
        g_lc1[n] = -0.5f * r.y;
        g_h[n]   = -0.5f * r.w - r.z;
    }
}

// ---------------- Kuu + kv^2*distfac ----------------
__global__ void k_kuu(const float* __restrict__ Z, const float* __restrict__ ls,
                      const float* __restrict__ kvp) {
    __shared__ float sZa[16][DIN+1], sZb[16][DIN+1], sil[DIN];
    int a0 = blockIdx.y * 16, b0 = blockIdx.x * 16;
    int tx = threadIdx.x, ty = threadIdx.y, tid = ty * 16 + tx;
    for (int i = tid; i < 16 * DIN; i += 256) {
        int r = i / DIN, q = i - r * DIN;
        sZa[r][q] = Z[(a0 + r) * DIN + q];
        sZb[r][q] = Z[(b0 + r) * DIN + q];
    }
    if (tid < DIN) { float L = ls[tid]; sil[tid] = 1.f / (L * L); }
    __syncthreads();
    float d2 = 0.f;
    #pragma unroll 16
    for (int q = 0; q < DIN; q++) {
        float d = sZa[ty][q] - sZb[tx][q];
        d2 = fmaf(d * d, sil[q], d2);
    }
    float kv = *kvp;
    int a = a0 + ty, b = b0 + tx;
    g_Kuu[a*MI + b] = kv * __expf(-0.5f * d2) + ((a == b) ? JITTERF : 0.f);
    g_pd[a*MI + b]  = kv * kv * __expf(-0.25f * d2);
}

// ---------------- psi1^T and F ----------------
__global__ void k_psi1F(const float* __restrict__ Z, const float* __restrict__ kvp) {
    __shared__ float sZ[16][DIN+1], sZq[16][DIN+1];
    __shared__ float sP[16][DIN+1], sR[16][DIN+1], sU[16][DIN+1], sW[16][DIN+1];
    int m0 = blockIdx.x * 16, n0 = blockIdx.y * 16;
    int tx = threadIdx.x, ty = threadIdx.y, tid = ty * 16 + tx;
    for (int i = tid; i < 16 * DIN; i += 256) {
        int r = i / DIN, q = i - r * DIN;
        float z = Z[(m0 + r) * DIN + q];
        sZ[r][q] = z; sZq[r][q] = z * z;
        int ni = (n0 + r) * DIN + q;
        sP[r][q] = g_P[ni]; sR[r][q] = g_R[ni];
        sU[r][q] = g_U[ni]; sW[r][q] = g_W[ni];
    }
    __syncthreads();
    float pz = 0.f, rz = 0.f, uz = 0.f, wz = 0.f;
    #pragma unroll 8
    for (int q = 0; q < DIN; q++) {
        float z = sZ[tx][q], zq = sZq[tx][q];
        pz = fmaf(sP[ty][q], z,  pz);
        rz = fmaf(sR[ty][q], zq, rz);
        uz = fmaf(sU[ty][q], z,  uz);
        wz = fmaf(sW[ty][q], zq, wz);
    }
    int n = n0 + ty, m = m0 + tx;
    float kv = *kvp;
    g_psi1T[m*NH + n] = kv * __expf(fmaf(-0.5f, g_a1[n] - 2.f * pz + rz, g_lc1[n]));
    g_F[n*MI + m]     = __expf(0.5f * g_h[n] + uz - 0.25f * wz);
}

// ---------------- big psi2 kernel (dyn smem, staged -0.5*W*Za) ----------------
__global__ void __launch_bounds__(256) k_psi2(const float* __restrict__ Z) {
    extern __shared__ float dsm[];
    float* sZa = dsm;
    float* sZb = sZa + DIN*64;
    float* sWZ = sZb + DIN*64;
    float* sW  = sWZ + DIN*64;
    float* sFa = sW + DIN;
    float* sFb = sFa + 64;
    int tp = blockIdx.x, ch = blockIdx.y;
    int a0 = c_ta[tp] * 64, b0 = c_tb[tp] * 64;
    int tid = threadIdx.x;
    for (int i = tid; i < 64 * DIN; i += 256) {
        int r = i & 63, q = i >> 6;
        sZa[q*64 + r] = Z[(a0 + r) * DIN + q];
        sZb[q*64 + r] = Z[(b0 + r) * DIN + q];
    }
    int tx = tid & 15, ty = tid >> 4;
    float acc[4][4] = {};
    int n0 = ch * CHUNK;
    int n1 = n0 + CHUNK; if (n1 > NH) n1 = NH;
    for (int n = n0; n < n1; n++) {
        __syncthreads();
        if (tid < DIN)                      sW[tid]        = g_W[n*DIN + tid];
        else if (tid >= 128 && tid < 192)   sFa[tid - 128] = g_F[n*MI + a0 + (tid - 128)];
        else if (tid >= 192)                sFb[tid - 192] = g_F[n*MI + b0 + (tid - 192)];
        __syncthreads();
        for (int i = tid; i < 64 * DIN; i += 256)
            sWZ[i] = -0.5f * sW[i >> 6] * sZa[i];
        __syncthreads();
        float C[4][4] = {};
        #pragma unroll 10
        for (int q = 0; q < DIN; q++) {
            float4 wa = *(const float4*)&sWZ[q*64 + tx*4];
            float4 zb = *(const float4*)&sZb[q*64 + ty*4];
            C[0][0] = fmaf(wa.x, zb.x, C[0][0]); C[0][1] = fmaf(wa.x, zb.y, C[0][1]);
            C[0][2] = fmaf(wa.x, zb.z, C[0][2]); C[0][3] = fmaf(wa.x, zb.w, C[0][3]);
            C[1][0] = fmaf(wa.y, zb.x, C[1][0]); C[1][1] = fmaf(wa.y, zb.y, C[1][1]);
            C[1][2] = fmaf(wa.y, zb.z, C[1][2]); C[1][3] = fmaf(wa.y, zb.w, C[1][3]);
            C[2][0] = fmaf(wa.z, zb.x, C[2][0]); C[2][1] = fmaf(wa.z, zb.y, C[2][1]);
            C[2][2] = fmaf(wa.z, zb.z, C[2][2]); C[2][3] = fmaf(wa.z, zb.w, C[2][3]);
            C[3][0] = fmaf(wa.w, zb.x, C[3][0]); C[3][1] = fmaf(wa.w, zb.y, C[3][1]);
            C[3][2] = fmaf(wa.w, zb.z, C[3][2]); C[3][3] = fmaf(wa.w, zb.w, C[3][3]);
        }
        float fa[4], fb[4];
        #pragma unroll
        for (int i = 0; i < 4; i++) { fa[i] = sFa[tx*4 + i]; fb[i] = sFb[ty*4 + i]; }
        #pragma unroll
        for (int i = 0; i < 4; i++)
            #pragma unroll
            for (int j = 0; j < 4; j++)
                acc[i][j] = fmaf(fa[i] * fb[j], __expf(C[i][j]), acc[i][j]);
    }
    float* part = &g_part[(size_t)ch * MI * MI];
    #pragma unroll
    for (int i = 0; i < 4; i++) {
        int a = a0 + tx * 4 + i;
        #pragma unroll
        for (int j = 0; j < 4; j++) {
            int b = b0 + ty * 4 + j;
            part[a*MI + b] = acc[i][j];
        }
    }
}

// deterministic chunk reduction + symmetrization + pd scaling
__global__ void k_reduce_psi2() {
    int a = blockIdx.x, b = threadIdx.x;
    int ta = a >> 6, tb = b >> 6;
    if (ta > tb) return;
    int idx = a * MI + b;
    float s = 0.f;
    #pragma unroll
    for (int ch = 0; ch < NCHUNK; ch++) s += g_part[ch * MI * MI + idx];
    float v = g_pd[idx] * s;
    g_psi2[idx] = v;
    if (ta < tb) g_psi2[b * MI + a] = v;
}

// ============ shared Cholesky body: packed lower in sL, scratch sD, recip in sdi ====
__device__ __forceinline__ void chol_body(float* sL, float* sD, float* sdi, int tid) {
    int lane = tid & 31, wid = tid >> 5;
    for (int K = 0; K < 4; K++) {
        int base = K * 64;
        for (int i = tid; i < 64 * 64; i += 1024) {
            int r = i >> 6, c = i & 63;
            if (c <= r) sD[r*65 + c] = sL[(((base+r)*(base+r+1))>>1) + base + c];
        }
        __syncthreads();
        if (wid == 0) {
            for (int k = 0; k < 64; k++) {
                if (lane == 0) {
                    float d = sqrtf(sD[k*65 + k]);
                    sD[k*65 + k] = d;
                    sdi[base + k] = 1.f / d;
                }
                __syncwarp();
                float inv = sdi[base + k];
                int r1 = lane + 32;
                if (lane > k) sD[lane*65 + k] *= inv;
                if (r1 > k)   sD[r1*65 + k]   *= inv;
                __syncwarp();
                float l0 = (lane > k) ? sD[lane*65 + k] : 0.f;
                float l1 = (r1 > k)   ? sD[r1*65 + k]   : 0.f;
                for (int j = k + 1; j <= lane; j++) sD[lane*65 + j] -= l0 * sD[j*65 + k];
                if (r1 > k)
                    for (int j = k + 1; j <= r1; j++) sD[r1*65 + j] -= l1 * sD[j*65 + k];
                __syncwarp();
            }
        }
        __syncthreads();
        for (int i = tid; i < 64 * 64; i += 1024) {
            int r = i >> 6, c = i & 63;
            if (c <= r) sL[(((base+r)*(base+r+1))>>1) + base + c] = sD[r*65 + c];
        }
        __syncthreads();
        int R = MI - base - 64;
        if (R > 0) {
            for (int rr = wid; rr < R; rr += 32) {
                int row = base + 64 + rr;
                int Pr = (row * (row + 1)) >> 1;
                float x0 = sL[Pr + base + lane];
                float x1 = sL[Pr + base + 32 + lane];
                #pragma unroll
                for (int m = 0; m < 64; m++) {
                    float src = (m < 32) ? x0 : x1;
                    float v = __shfl_sync(0xffffffffu, src, m & 31);
                    float xm = v * sdi[base + m];
                    if (m < 32) {
                        if (lane == m) x0 = xm;
                        if (lane > m)  x0 -= xm * sD[lane*65 + m];
                        x1 -= xm * sD[(lane+32)*65 + m];
                    } else {
                        if (lane == m - 32) x1 = xm;
                        if (lane + 32 > m)  x1 -= xm * sD[(lane+32)*65 + m];
                    }
                }
                sL[Pr + base + lane]      = x0;
                sL[Pr + base + 32 + lane] = x1;
            }
            __syncthreads();
            int T = R >> 5;
            int ntiles = (T * (T + 1)) >> 1;
            int g = tid >> 6, gt = tid & 63;
            int txx = gt & 7, tyy = gt >> 3;
            for (int tile = g; tile < ntiles; tile += 16) {
                int ti = 0, rem = tile;
                while (rem > ti) { rem -= (ti + 1); ti++; }
                int tj = rem;
                int gr = base + 64 + ti * 32, gc = base + 64 + tj * 32;
                int Pr[4], Pc[4];
                #pragma unroll
                for (int i = 0; i < 4; i++) { int r = gr + tyy*4 + i; Pr[i] = ((r*(r+1))>>1) + base; }
                #pragma unroll
                for (int j = 0; j < 4; j++) { int c = gc + txx*4 + j; Pc[j] = ((c*(c+1))>>1) + base; }
                float acc[4][4] = {};
                #pragma unroll 16
                for (int k = 0; k < 64; k++) {
                    float la[4], lb[4];
                    #pragma unroll
                    for (int i = 0; i < 4; i++) la[i] = sL[Pr[i] + k];
                    #pragma unroll
                    for (int j = 0; j < 4; j++) lb[j] = sL[Pc[j] + k];
                    #pragma unroll
                    for (int i = 0; i < 4; i++)
                        #pragma unroll
                        for (int j = 0; j < 4; j++)
                            acc[i][j] = fmaf(la[i], lb[j], acc[i][j]);
                }
                #pragma unroll
                for (int i = 0; i < 4; i++) {
                    int r = gr + tyy*4 + i;
                    int Prow = (r * (r + 1)) >> 1;
                    #pragma unroll
                    for (int j = 0; j < 4; j++) {
                        int c = gc + txx*4 + j;
                        if (c <= r) sL[Prow + c] -= acc[i][j];
                    }
                }
            }
        }
        __syncthreads();
    }
}

// chol(Kuu) -> packed L in global + dinv
__global__ void __launch_bounds__(1024) k_chol256(const float* __restrict__ A,
                                                  float* __restrict__ Lp,
                                                  float* __restrict__ dinv) {
    extern __shared__ float sm[];
    float* sL  = sm;
    float* sD  = sm + PACKED;
    float* sdi = sD + 64*65;
    int tid = threadIdx.x;
    {
        int r = tid >> 2, sub = tid & 3;
        int Pr = (r * (r + 1)) >> 1;
        for (int c = sub; c <= r; c += 4) sL[Pr + c] = A[r * MI + c];
    }
    __syncthreads();
    chol_body(sL, sD, sdi, tid);
    {
        int r = tid >> 2, sub = tid & 3;
        int Pr = (r * (r + 1)) >> 1;
        for (int c = sub; c <= r; c += 4) Lp[Pr + c] = sL[Pr + c];
    }
    if (tid < MI) dinv[tid] = sdi[tid];
}

// ============ column solve core (register-resident, packed L in SMEM) ============
__device__ __forceinline__ void solve_core(const float* sLp, const float* sdi,
                                           const float* __restrict__ B, int ldb, int transB,
                                           float* __restrict__ X, int ldx,
                                           float scale, int col, int lane) {
    float x[8];
    int Pt[8];
    #pragma unroll
    for (int t = 0; t < 8; t++) {
        int j = lane + 32 * t;
        Pt[t] = (j * (j + 1)) >> 1;
        x[t] = transB ? B[col * ldb + j] : B[j * ldb + col];
    }
    #pragma unroll
    for (int s = 0; s < 8; s++) {
        #pragma unroll
        for (int mm = 0; mm < 32; mm++) {
            int m = s * 32 + mm;
            float xm = __shfl_sync(0xffffffffu, x[s], mm) * sdi[m];
            if (lane == mm) x[s] = xm;
            if (lane > mm)  x[s] -= xm * sLp[Pt[s] + m];
            #pragma unroll
            for (int t = s + 1; t < 8; t++)
                x[t] -= xm * sLp[Pt[t] + m];
        }
    }
    #pragma unroll
    for (int t = 0; t < 8; t++)
        X[(lane + 32 * t) * ldx + col] = x[t] * scale;
}

// solve1: Tmp = L^{-1} psi2 (transB, psi2 symmetric)
__global__ void __launch_bounds__(256) k_solve1(const float* __restrict__ Lp,
                                                const float* __restrict__ dinv) {
    extern __shared__ float sm[];
    float* sLp = sm;
    float* sdi = sm + PACKED;
    int tid = threadIdx.x, lane = tid & 31, wid = tid >> 5;
    for (int i = tid; i < PACKED; i += 256) sLp[i] = Lp[i];
    if (tid < MI) sdi[tid] = dinv[tid];
    __syncthreads();
    solve_core(sLp, sdi, g_psi2, MI, 1, g_tmp, MI, 1.0f, blockIdx.x * 8 + wid, lane);
}

// solve2 + H: blocks<32: AAT = L^{-1} Tmp^T / sigma2 ; blocks 32,33: H = L^{-1} G
__global__ void __launch_bounds__(256) k_solve2H(const float* __restrict__ Lp,
                                                 const float* __restrict__ dinv) {
    extern __shared__ float sm[];
    float* sLp = sm;
    float* sdi = sm + PACKED;
    int tid = threadIdx.x, lane = tid & 31, wid = tid >> 5;
    for (int i = tid; i < PACKED; i += 256) sLp[i] = Lp[i];
    if (tid < MI) sdi[tid] = dinv[tid];
    __syncthreads();
    if (blockIdx.x < 32) {
        solve_core(sLp, sdi, g_tmp, MI, 1, g_AAT, MI, 1000.0f, blockIdx.x * 8 + wid, lane);
    } else {
        int col = (blockIdx.x - 32) * 8 + wid;
        if (col < DO)
            solve_core(sLp, sdi, g_G, DO, 0, g_H, DO, 1.0f, col, lane);
    }
}

// ---------------- G = psi1^T @ Y  [MI x DO] ----------------
__global__ void k_gemm_G(const float* __restrict__ Y) {
    int m = blockIdx.x, tid = threadIdx.x;  // 128 threads
    float acc[DO] = {};
    for (int n = tid; n < NH; n += 128) {
        float a = g_psi1T[m * NH + n];
        const float4* y4 = (const float4*)&Y[n * DO];
        #pragma unroll
        for (int d4 = 0; d4 < 4; d4++) {
            float4 y = y4[d4];
            acc[4*d4 + 0] = fmaf(a, y.x, acc[4*d4 + 0]);
            acc[4*d4 + 1] = fmaf(a, y.y, acc[4*d4 + 1]);
            acc[4*d4 + 2] = fmaf(a, y.z, acc[4*d4 + 2]);
            acc[4*d4 + 3] = fmaf(a, y.w, acc[4*d4 + 3]);
        }
    }
    __shared__ float sred[128];
    for (int d = 0; d < DO; d++) {
        sred[tid] = acc[d];
        __syncthreads();
        for (int s = 64; s > 0; s >>= 1) {
            if (tid < s) sred[tid] += sred[tid + s];
            __syncthreads();
        }
        if (tid == 0) g_G[m * DO + d] = sred[0];
        __syncthreads();
    }
}

// ====== finish: chol(AAT+I) in SMEM, c = LB^{-1} H / sigma2, bound assembly ======
__global__ void __launch_bounds__(1024) k_finish(const float* __restrict__ Y,
                                                 const float* __restrict__ kvp,
                                                 float* __restrict__ out) {
    extern __shared__ float smf[];
    double* sred = (double*)smf;                 // 1024 doubles (8KB, 8-aligned at base)
    float* sL    = smf + 2048;                   // PACKED
    float* sD    = sL + PACKED;                  // 64*65 (reused as c-buffer later)
    float* sdi   = sD + 64*65;                   // 256
    float* sdiag = sdi + 256;                    // 256 (AAT diag for trace)
    int tid = threadIdx.x, lane = tid & 31, wid = tid >> 5;

    {   // load AAT + I packed; capture AAT diagonal for trace
        int r = tid >> 2, sub = tid & 3;
        int Pr = (r * (r + 1)) >> 1;
        for (int c = sub; c <= r; c += 4) {
            float v = g_AAT[r * MI + c];
            if (c == r) { sdiag[r] = v; v += 1.f; }
            sL[Pr + c] = v;
        }
    }
    __syncthreads();
    chol_body(sL, sD, sdi, tid);   // ends with __syncthreads

    // c = LB^{-1} H * 1000, into sD region as [256 x 16]
    if (wid < DO) {
        float x[8];
        int Pt[8];
        #pragma unroll
        for (int t = 0; t < 8; t++) {
            int j = lane + 32 * t;
            Pt[t] = (j * (j + 1)) >> 1;
            x[t] = g_H[j * DO + wid];
        }
        #pragma unroll
        for (int s = 0; s < 8; s++) {
            #pragma unroll
            for (int mm = 0; mm < 32; mm++) {
                int m = s * 32 + mm;
                float xm = __shfl_sync(0xffffffffu, x[s], mm) * sdi[m];
                if (lane == mm) x[s] = xm;
                if (lane > mm)  x[s] -= xm * sL[Pt[s] + m];
                #pragma unroll
                for (int t = s + 1; t < 8; t++)
                    x[t] -= xm * sL[Pt[t] + m];
            }
        }
        #pragma unroll
        for (int t = 0; t < 8; t++)
            sD[(lane + 32 * t) * DO + wid] = x[t] * 1000.0f;
    }
    __syncthreads();

    // reductions in double
    double y2 = 0.0, c2 = 0.0, tr = 0.0, ld = 0.0;
    for (int i = tid; i < NH * DO; i += 1024) { double y = Y[i]; y2 = fma(y, y, y2); }
    for (int i = tid; i < MI * DO; i += 1024) { double v = sD[i]; c2 = fma(v, v, c2); }
    if (tid < MI) {
        tr = (double)sdiag[tid];
        ld = -log((double)sdi[tid]);
    }
    double vals[4] = { y2, c2, tr, ld };
    double res[4];
    for (int v = 0; v < 4; v++) {
        sred[tid] = vals[v];
        __syncthreads();
        for (int s = 512; s > 0; s >>= 1) {
            if (tid < s) sred[tid] += sred[tid + s];
            __syncthreads();
        }
        res[v] = sred[0];
        __syncthreads();
    }
    if (tid == 0) {
        double sigma2 = 1.0e-3;
        double kv = (double)(*kvp);
        double psi0 = (double)NH * kv;
        double bound = -0.5 * (double)NH * (double)DO * log(2.0 * M_PI * sigma2);
        bound -= 0.5 / sigma2 * res[0];
        bound -= 0.5 * (double)DO * (psi0 / sigma2 - res[2]);
        bound -= (double)DO * res[3];
        bound += 0.5 * res[1];
        out[0] = (float)bound;
    }
}

// ---------------- stream/event resources (host objects, created at static init) ----
struct StreamInit {
    cudaStream_t s2;
    cudaEvent_t evA, evP, evB;
    bool ok;
    StreamInit() : s2(nullptr), ok(false) {
        if (cudaStreamCreateWithFlags(&s2, cudaStreamNonBlocking) != cudaSuccess) return;
        if (cudaEventCreateWithFlags(&evA, cudaEventDisableTiming) != cudaSuccess) return;
        if (cudaEventCreateWithFlags(&evP, cudaEventDisableTiming) != cudaSuccess) return;
        if (cudaEventCreateWithFlags(&evB, cudaEventDisableTiming) != cudaSuccess) return;
        ok = true;
    }
};
static StreamInit g_si;

// ---------------- host launcher ----------------
extern "C" void kernel_launch(void* const* d_in, const int* in_sizes, int n_in,
                              void* d_out, int out_size) {
    const float* Xm = (const float*)d_in[0];
    const float* Xv = (const float*)d_in[1];
    const float* Z  = (const float*)d_in[2];
    const float* Y  = (const float*)d_in[3];
    const float* kv = (const float*)d_in[4];
    const float* ls = (const float*)d_in[5];
    float* out = (float*)d_out;

    float *pKuu, *pLp, *pDA;
    cudaGetSymbolAddress((void**)&pKuu, g_Kuu);
    cudaGetSymbolAddress((void**)&pLp,  g_Lp);
    cudaGetSymbolAddress((void**)&pDA,  g_dinvA);

    const int PSI2_SMEM   = (3 * DIN * 64 + DIN + 128) * (int)sizeof(float);
    const int CHOL_SMEM   = (PACKED + 64*65 + 256) * (int)sizeof(float);
    const int SOLVE_SMEM  = (PACKED + 256) * (int)sizeof(float);
    const int FINISH_SMEM = 2048 * (int)sizeof(float) + (PACKED + 64*65 + 256 + 256) * (int)sizeof(float);
    cudaFuncSetAttribute(k_psi2,    cudaFuncAttributeMaxDynamicSharedMemorySize, PSI2_SMEM);
    cudaFuncSetAttribute(k_chol256, cudaFuncAttributeMaxDynamicSharedMemorySize, CHOL_SMEM);
    cudaFuncSetAttribute(k_solve1,  cudaFuncAttributeMaxDynamicSharedMemorySize, SOLVE_SMEM);
    cudaFuncSetAttribute(k_solve2H, cudaFuncAttributeMaxDynamicSharedMemorySize, SOLVE_SMEM);
    cudaFuncSetAttribute(k_finish,  cudaFuncAttributeMaxDynamicSharedMemorySize, FINISH_SMEM);

    if (g_si.ok) {
        cudaStream_t s2 = g_si.s2;
        // fork: side chain (kuu -> chol -> gemm_G) runs under psi2
        cudaEventRecord(g_si.evA, 0);
        cudaStreamWaitEvent(s2, g_si.evA, 0);
        k_kuu<<<dim3(16, 16), dim3(16, 16), 0, s2>>>(Z, ls, kv);
        k_chol256<<<1, 1024, CHOL_SMEM, s2>>>(pKuu, pLp, pDA);

        k_prep<<<NH, 128>>>(Xm, Xv, ls);
        k_psi1F<<<dim3(16, 125), dim3(16, 16)>>>(Z, kv);
        cudaEventRecord(g_si.evP, 0);
        cudaStreamWaitEvent(s2, g_si.evP, 0);
        k_gemm_G<<<MI, 128, 0, s2>>>(Y);
        cudaEventRecord(g_si.evB, s2);

        k_psi2<<<dim3(10, NCHUNK), 256, PSI2_SMEM>>>(Z);
        k_reduce_psi2<<<256, 256>>>();
        cudaStreamWaitEvent(0, g_si.evB, 0);   // join side chain
        k_solve1<<<32, 256, SOLVE_SMEM>>>(pLp, pDA);
        k_solve2H<<<34, 256, SOLVE_SMEM>>>(pLp, pDA);
        k_finish<<<1, 1024, FINISH_SMEM>>>(Y, kv, out);
    } else {
        // sequential fallback
        k_prep<<<NH, 128>>>(Xm, Xv, ls);
        k_kuu<<<dim3(16, 16), dim3(16, 16)>>>(Z, ls, kv);
        k_chol256<<<1, 1024, CHOL_SMEM>>>(pKuu, pLp, pDA);
        k_psi1F<<<dim3(16, 125), dim3(16, 16)>>>(Z, kv);
        k_gemm_G<<<MI, 128>>>(Y);
        k_psi2<<<dim3(10, NCHUNK), 256, PSI2_SMEM>>>(Z);
        k_reduce_psi2<<<256, 256>>>();
        k_solve1<<<32, 256, SOLVE_SMEM>>>(pLp, pDA);
        k_solve2H<<<34, 256, SOLVE_SMEM>>>(pLp, pDA);
        k_finish<<<1, 1024, FINISH_SMEM>>>(Y, kv, out);
    }
}